// round 2
// baseline (speedup 1.0000x reference)
#include <cuda_runtime.h>
#include <math.h>

// Problem constants (fixed by reference setup_inputs)
#define B 32
#define H 64
#define W 64
#define C 256
#define SPATIAL (H * W)          // 4096
#define NCHUNK 32                // spatial chunks per batch for stage-1 reduce
#define ROWS_PER_CHUNK (SPATIAL / NCHUNK)   // 128
#define X_ELEMS (B * SPATIAL * C)           // 33554432
#define BN_EPS 1e-3f

// Stage-1 partials (deterministic two-level reduction; no float atomics)
__device__ float g_psum[B][NCHUNK][C];
__device__ float g_pmax[B][NCHUNK][C];

// ---------------------------------------------------------------------------
// Kernel A: per-(batch,chunk) partial sum & max over 128 spatial rows,
// 256 threads = 256 channels -> fully coalesced 1KB row reads.
// ---------------------------------------------------------------------------
__global__ __launch_bounds__(C) void pool_partial_kernel(const float* __restrict__ in)
{
    const int c     = threadIdx.x;
    const int chunk = blockIdx.x;
    const int b     = blockIdx.y;

    const float* p = in + ((size_t)(b * SPATIAL + chunk * ROWS_PER_CHUNK)) * C + c;

    float s0 = 0.f, s1 = 0.f, s2 = 0.f, s3 = 0.f;
    float m0 = -INFINITY, m1 = -INFINITY, m2 = -INFINITY, m3 = -INFINITY;

#pragma unroll 8
    for (int r = 0; r < ROWS_PER_CHUNK; r += 4) {
        float v0 = p[(size_t)(r + 0) * C];
        float v1 = p[(size_t)(r + 1) * C];
        float v2 = p[(size_t)(r + 2) * C];
        float v3 = p[(size_t)(r + 3) * C];
        s0 += v0; s1 += v1; s2 += v2; s3 += v3;
        m0 = fmaxf(m0, v0); m1 = fmaxf(m1, v1);
        m2 = fmaxf(m2, v2); m3 = fmaxf(m3, v3);
    }
    g_psum[b][chunk][c] = (s0 + s1) + (s2 + s3);
    g_pmax[b][chunk][c] = fmaxf(fmaxf(m0, m1), fmaxf(m2, m3));
}

// ---------------------------------------------------------------------------
// Kernel B: one block per batch. Finish pool reduction (fixed order),
// blend avg/max, dense 256x256 + bias, BN, ReLU, per-channel 2-logit
// gumbel-softmax hard gate. Writes gate into the output tail.
// ---------------------------------------------------------------------------
__global__ __launch_bounds__(C) void gate_kernel(
    const float* __restrict__ factor,   // (2,)
    const float* __restrict__ W1,       // (C, C) row-major (c_in, c_out)
    const float* __restrict__ b1,       // (C,)
    const float* __restrict__ gamma,
    const float* __restrict__ beta,
    const float* __restrict__ bn_mean,
    const float* __restrict__ bn_var,
    const float* __restrict__ Wg,       // (C, 2)
    const float* __restrict__ bg,       // (C, 2)
    const float* __restrict__ gumbel,   // (B, C, 2)
    float* __restrict__ gate_out)       // (B, C)  == d_out + X_ELEMS
{
    __shared__ float pool_s[C];
    const int b = blockIdx.x;
    const int t = threadIdx.x;

    // finish reduction for channel t (deterministic sequential order)
    {
        float s = 0.f;
        float m = -INFINITY;
#pragma unroll
        for (int k = 0; k < NCHUNK; ++k) {
            s += g_psum[b][k][t];
            m = fmaxf(m, g_pmax[b][k][t]);
        }
        const float avg = s * (1.0f / (float)SPATIAL);

        // softmax over the 2 blend factors
        const float a0 = factor[0], a1 = factor[1];
        const float fm = fmaxf(a0, a1);
        const float e0 = expf(a0 - fm), e1 = expf(a1 - fm);
        const float inv = 1.0f / (e0 + e1);
        pool_s[t] = avg * (e0 * inv) + m * (e1 * inv);
    }
    __syncthreads();

    // dense: h[t] = pool . W1[:, t] + b1[t]
    float acc = 0.f;
#pragma unroll 8
    for (int k = 0; k < C; ++k)
        acc = fmaf(pool_s[k], W1[k * C + t], acc);
    float h = acc + b1[t];

    // BN (inference) + ReLU
    h = gamma[t] * (h - bn_mean[t]) * (1.0f / sqrtf(bn_var[t] + BN_EPS)) + beta[t];
    h = fmaxf(h, 0.f);

    // grouped conv: 2 logits per channel, + gumbel, softmax, hard ST gate
    const float l0 = fmaf(h, Wg[t * 2 + 0], bg[t * 2 + 0]);
    const float l1 = fmaf(h, Wg[t * 2 + 1], bg[t * 2 + 1]);
    const float z0 = l0 + gumbel[(b * C + t) * 2 + 0];
    const float z1 = l1 + gumbel[(b * C + t) * 2 + 1];
    const float zm = fmaxf(z0, z1);
    const float q0 = expf(z0 - zm), q1 = expf(z1 - zm);
    const float y1 = q1 / (q0 + q1);
    const float hard1 = (z1 > z0) ? 1.0f : 0.0f;   // jnp.argmax tie -> index 0
    // numerically matches stop_gradient(hard - y) + y
    gate_out[b * C + t] = (hard1 - y1) + y1;
}

// ---------------------------------------------------------------------------
// Kernel C: x = inputs * gate (float4 vectorized). Gate (32KB) stays in cache.
// ---------------------------------------------------------------------------
__global__ __launch_bounds__(256) void apply_gate_kernel(
    const float4* __restrict__ in4,
    const float* __restrict__ gate,   // (B, C)
    float4* __restrict__ out4)
{
    const int idx = blockIdx.x * blockDim.x + threadIdx.x;  // < X_ELEMS/4
    const int fidx = idx << 2;
    const int c = fidx & (C - 1);
    const int b = fidx >> 20;            // SPATIAL*C = 2^20
    const float4 v = in4[idx];
    const float4 g = *reinterpret_cast<const float4*>(&gate[b * C + c]);
    float4 r;
    r.x = v.x * g.x; r.y = v.y * g.y; r.z = v.z * g.z; r.w = v.w * g.w;
    out4[idx] = r;
}

extern "C" void kernel_launch(void* const* d_in, const int* in_sizes, int n_in,
                              void* d_out, int out_size)
{
    const float* inputs = (const float*)d_in[0];
    const float* factor = (const float*)d_in[1];
    const float* W1     = (const float*)d_in[2];
    const float* b1     = (const float*)d_in[3];
    const float* gamma  = (const float*)d_in[4];
    const float* beta   = (const float*)d_in[5];
    const float* bnm    = (const float*)d_in[6];
    const float* bnv    = (const float*)d_in[7];
    const float* Wg     = (const float*)d_in[8];
    const float* bg     = (const float*)d_in[9];
    const float* gumbel = (const float*)d_in[10];

    float* out = (float*)d_out;
    float* gate_out = out + X_ELEMS;   // (B, C) broadcast gate lives after x

    dim3 gridA(NCHUNK, B);
    pool_partial_kernel<<<gridA, C>>>(inputs);

    gate_kernel<<<B, C>>>(factor, W1, b1, gamma, beta, bnm, bnv, Wg, bg,
                          gumbel, gate_out);

    apply_gate_kernel<<<X_ELEMS / 4 / 256, 256>>>(
        (const float4*)inputs, gate_out, (float4*)out);
}